// round 10
// baseline (speedup 1.0000x reference)
#include <cuda_runtime.h>
#include <cuda_fp16.h>
#include <cstdint>

// ---------------------------------------------------------------------------
// JointNetwork: out[b,t,u,:] = tanh(a[bt,:] + t[bu,:]) @ W_j + b_j
//   big GEMM: M=204800, K=640, N=512, fp32 out
// R9: M64xN64 warp tile (crossbar/tensor ratio 0.75 -> 0.5).
//     CTA 256thr (8 warps 2x4) tile M128xN256, K in 10x64 double-buffered.
// ---------------------------------------------------------------------------
#define HID   640
#define NCLS  512

__device__ __half g_a[2048 * HID];   // audio projection, fp16
__device__ __half g_t[400 * HID];    // text projection, fp16
__device__ __half g_wj[NCLS * HID];  // W_j^T as [v][h] (K-major B rows), fp16

// SMEM: A stages 16KB @ {0,16K}; B stages 32KB @ {32K,64K}; total 96KB
#define SA_STAGE(s) ((uint32_t)(s) * 16384u)
#define SB_STAGE(s) (32768u + (uint32_t)(s) * 32768u)
#define SMEM_BYTES  98304u

// ---------------------------------------------------------------------------
__device__ __forceinline__ uint32_t smem_u32(const void* p) {
    uint32_t a;
    asm("{ .reg .u64 t; cvta.to.shared.u64 t, %1; cvt.u32.u64 %0, t; }" : "=r"(a) : "l"(p));
    return a;
}
__device__ __forceinline__ uint32_t swz128(uint32_t off) { return off ^ ((off >> 3) & 0x70); }

__device__ __forceinline__ float tanh_fast(float x) {
    float e;
    asm("ex2.approx.f32 %0, %1;" : "=f"(e) : "f"(x * 2.8853900817779268f)); // e^{2x}
    float r;
    asm("rcp.approx.f32 %0, %1;" : "=f"(r) : "f"(e + 1.0f));
    return fmaf(-2.0f, r, 1.0f);
}

#define CP_ASYNC16(dst_u32, src_ptr) \
    asm volatile("cp.async.cg.shared.global [%0], [%1], 16;" \
        :: "r"(dst_u32), "l"(src_ptr) : "memory")
#define CP_ASYNC_COMMIT() asm volatile("cp.async.commit_group;" ::: "memory")
#define CP_ASYNC_WAIT0()  asm volatile("cp.async.wait_group 0;" ::: "memory")

#define LDSM_X4(r0, r1, r2, r3, addr) \
    asm volatile("ldmatrix.sync.aligned.m8n8.x4.shared.b16 {%0,%1,%2,%3}, [%4];" \
        : "=r"(r0), "=r"(r1), "=r"(r2), "=r"(r3) : "r"(addr))

#define MMA16816(d, a, b) \
    asm volatile("mma.sync.aligned.m16n8k16.row.col.f32.f16.f16.f32 " \
        "{%0,%1,%2,%3}, {%4,%5,%6,%7}, {%8,%9}, {%0,%1,%2,%3};" \
        : "+f"((d)[0]), "+f"((d)[1]), "+f"((d)[2]), "+f"((d)[3]) \
        : "r"((a)[0]), "r"((a)[1]), "r"((a)[2]), "r"((a)[3]), "r"((b)[0]), "r"((b)[1]))

// ---------------------------------------------------------------------------
// Fused prep: blocks [0,320) audio proj, [320,390) text proj, [390,1670) Wj cvt
// ---------------------------------------------------------------------------
__device__ void sgemm_body(const float* __restrict__ A, const float* __restrict__ W,
                           const float* __restrict__ bias, __half* __restrict__ C,
                           int M, int K, int bx, int by)
{
    __shared__ float As[16][68];
    __shared__ float Bs[16][64];
    const int N = HID;
    int tid = threadIdx.x;
    int bm = by * 64, bn = bx * 64;
    int tx = tid & 15, ty = tid >> 4;
    int ar = tid >> 2, ak = (tid & 3) * 4;
    int bk = tid >> 4, bn4 = (tid & 15) * 4;
    float acc[4][4] = {};

    for (int k0 = 0; k0 < K; k0 += 16) {
        float4 av = make_float4(0.f, 0.f, 0.f, 0.f);
        if (bm + ar < M) av = *(const float4*)(A + (size_t)(bm + ar) * K + k0 + ak);
        As[ak + 0][ar] = av.x; As[ak + 1][ar] = av.y;
        As[ak + 2][ar] = av.z; As[ak + 3][ar] = av.w;
        *(float4*)&Bs[bk][bn4] = *(const float4*)(W + (size_t)(k0 + bk) * N + bn + bn4);
        __syncthreads();
#pragma unroll
        for (int k = 0; k < 16; k++) {
            float4 a4 = *(const float4*)&As[k][ty * 4];
            float4 b4 = *(const float4*)&Bs[k][tx * 4];
            float aa[4] = {a4.x, a4.y, a4.z, a4.w};
            float bb[4] = {b4.x, b4.y, b4.z, b4.w};
#pragma unroll
            for (int i = 0; i < 4; i++)
#pragma unroll
                for (int j = 0; j < 4; j++) acc[i][j] += aa[i] * bb[j];
        }
        __syncthreads();
    }
#pragma unroll
    for (int i = 0; i < 4; i++) {
        int m = bm + ty * 4 + i;
        if (m < M) {
#pragma unroll
            for (int j = 0; j < 4; j++) {
                int n = bn + tx * 4 + j;
                C[(size_t)m * N + n] = __float2half_rn(acc[i][j] + bias[n]);
            }
        }
    }
}

__global__ __launch_bounds__(256) void prep_kernel(
    const float* __restrict__ audio, const float* __restrict__ text,
    const float* __restrict__ W_a, const float* __restrict__ b_a,
    const float* __restrict__ W_t, const float* __restrict__ b_t,
    const float* __restrict__ W_j)
{
    int blk = blockIdx.x;
    if (blk < 320) {
        sgemm_body(audio, W_a, b_a, g_a, 2048, 512, blk % 10, blk / 10);
    } else if (blk < 390) {
        int b = blk - 320;
        sgemm_body(text, W_t, b_t, g_t, 400, 320, b % 10, b / 10);
    } else {
        int idx = (blk - 390) * 256 + threadIdx.x;   // [0, 327680)
        int v = idx / HID;
        int h = idx - v * HID;
        g_wj[idx] = __float2half_rn(W_j[h * NCLS + v]);
    }
}

// ---------------------------------------------------------------------------
// Main HMMA kernel: 256 thr (8 warps, 2x4), CTA tile M128 x N256,
// warp tile M64 x N64, K in 10 chunks of 64, double-buffered.
// ---------------------------------------------------------------------------
static constexpr int THREADS = 256;
static constexpr int KCHUNKS = 10;

__global__ __launch_bounds__(THREADS, 1) void joint_main_kernel(
    const float* __restrict__ b_j, float* __restrict__ out)
{
    extern __shared__ __align__(1024) char smem[];
    const uint32_t sb = smem_u32(smem);
    const int tid  = threadIdx.x;
    const int lane = tid & 31;
    const int wid  = tid >> 5;
    const int warp_m = wid & 1;    // 0..1 (64-row slab)
    const int warp_n = wid >> 1;   // 0..3 (64-col slab)
    const int m0 = blockIdx.x * 128;
    const int n0 = blockIdx.y * 256;

    // producer: 512 quarter-tasks (128 rows x 4 quarters), 2 per thread
    // task q: pr = q>>2 (row), pq = q&3 (16-half quarter)
    const int q0 = tid, q1 = tid + 256;
    const int pr0 = q0 >> 2, pq0 = q0 & 3;
    const int pr1 = q1 >> 2, pq1 = q1 & 3;
    const int mA0 = m0 + pr0, mA1 = m0 + pr1;
    const int bt0 = mA0 / 100, u0 = mA0 - bt0 * 100;
    const int bt1 = mA1 / 100, u1 = mA1 - bt1 * 100;
    const __half* rowa0 = g_a + bt0 * HID + pq0 * 16;
    const __half* rowt0 = g_t + (((bt0 >> 9) * 100) + u0) * HID + pq0 * 16;
    const __half* rowa1 = g_a + bt1 * HID + pq1 * 16;
    const __half* rowt1 = g_t + (((bt1 >> 9) * 100) + u1) * HID + pq1 * 16;
    const uint32_t aoff0 = (uint32_t)(pr0 * 128 + pq0 * 32);
    const uint32_t aoff1 = (uint32_t)(pr1 * 128 + pq1 * 32);

    // B cp.async mapping: 8 x 16B per thread per chunk (256 rows x 8 chunks)
    const int b_row0  = tid >> 3;     // 0..31, +32 per i
    const int b_chunk = tid & 7;
    const __half* wj_base = g_wj + (size_t)(n0 + b_row0) * HID + b_chunk * 8;

    float acc[4][8][4];
#pragma unroll
    for (int mt = 0; mt < 4; mt++)
#pragma unroll
        for (int nt = 0; nt < 8; nt++)
#pragma unroll
            for (int q = 0; q < 4; q++) acc[mt][nt][q] = 0.f;

    auto loadB = [&](int c, int s) {
        const __half* src = wj_base + c * 64;
#pragma unroll
        for (int i = 0; i < 8; i++) {
            uint32_t off = (uint32_t)((b_row0 + i * 32) * 128 + b_chunk * 16);
            CP_ASYNC16(sb + SB_STAGE(s) + swz128(off), src + (size_t)i * 32 * HID);
        }
        CP_ASYNC_COMMIT();
    };

    // tanh 8 halves from (av, tv) -> stage s at (base quarter off + j*16)
    auto tanh_store = [&](uint4 av, uint4 tv, uint32_t aoff, int j, int s) {
        const __half2* ah = (const __half2*)&av;
        const __half2* th = (const __half2*)&tv;
        uint32_t rs[4];
#pragma unroll
        for (int q = 0; q < 4; q++) {
            float2 af = __half22float2(ah[q]);
            float2 tf = __half22float2(th[q]);
            __half2 h = __floats2half2_rn(tanh_fast(af.x + tf.x), tanh_fast(af.y + tf.y));
            rs[q] = *(uint32_t*)&h;
        }
        *(uint4*)(smem + SA_STAGE(s) + swz128(aoff + (uint32_t)j * 16)) =
            make_uint4(rs[0], rs[1], rs[2], rs[3]);
    };

    // ---- prologue: produce chunk 0 (both tasks), start B chunk 0 ----
    {
        uint4 a00 = *(const uint4*)rowa0, t00 = *(const uint4*)rowt0;
        uint4 a01 = *(const uint4*)(rowa0 + 8), t01 = *(const uint4*)(rowt0 + 8);
        uint4 a10 = *(const uint4*)rowa1, t10 = *(const uint4*)rowt1;
        uint4 a11 = *(const uint4*)(rowa1 + 8), t11 = *(const uint4*)(rowt1 + 8);
        tanh_store(a00, t00, aoff0, 0, 0);
        tanh_store(a01, t01, aoff0, 1, 0);
        tanh_store(a10, t10, aoff1, 0, 0);
        tanh_store(a11, t11, aoff1, 1, 0);
    }
    loadB(0, 0);

    // ---- main loop ----
    for (int c = 0; c < KCHUNKS; c++) {
        const int s = c & 1;
        CP_ASYNC_WAIT0();
        __syncthreads();                 // stage s ready; stage s^1 free

        const bool more = (c + 1 < KCHUNKS);
        if (more) loadB(c + 1, s ^ 1);

        // prefetch next-chunk producer inputs (used at ks boundaries)
        uint4 a00, t00, a01, t01, a10, t10, a11, t11;
        if (more) {
            const __half* pa0 = rowa0 + (c + 1) * 64;
            const __half* pt0 = rowt0 + (c + 1) * 64;
            const __half* pa1 = rowa1 + (c + 1) * 64;
            const __half* pt1 = rowt1 + (c + 1) * 64;
            a00 = *(const uint4*)pa0;       t00 = *(const uint4*)pt0;
            a01 = *(const uint4*)(pa0 + 8); t01 = *(const uint4*)(pt0 + 8);
            a10 = *(const uint4*)pa1;       t10 = *(const uint4*)pt1;
            a11 = *(const uint4*)(pa1 + 8); t11 = *(const uint4*)(pt1 + 8);
        }

        const uint32_t aBase = sb + SA_STAGE(s);
        const uint32_t bBase = sb + SB_STAGE(s);

#pragma unroll
        for (int ks = 0; ks < 4; ks++) {
            uint32_t afr[4][4];
#pragma unroll
            for (int mt = 0; mt < 4; mt++) {
                int row = warp_m * 64 + mt * 16 + (lane & 15);
                uint32_t off = (uint32_t)(row * 128 + ks * 32 + (lane >> 4) * 16);
                LDSM_X4(afr[mt][0], afr[mt][1], afr[mt][2], afr[mt][3], aBase + swz128(off));
            }
            uint32_t bfr[8][2];
#pragma unroll
            for (int p = 0; p < 4; p++) {
                int tl = lane >> 3, rr = lane & 7;
                int row = warp_n * 64 + p * 16 + (tl >> 1) * 8 + rr;
                uint32_t off = (uint32_t)(row * 128 + ks * 32 + (tl & 1) * 16);
                uint32_t r0, r1, r2, r3;
                LDSM_X4(r0, r1, r2, r3, bBase + swz128(off));
                bfr[p * 2 + 0][0] = r0; bfr[p * 2 + 0][1] = r1;
                bfr[p * 2 + 1][0] = r2; bfr[p * 2 + 1][1] = r3;
            }

#pragma unroll
            for (int mt = 0; mt < 4; mt++)
#pragma unroll
                for (int nt = 0; nt < 8; nt++)
                    MMA16816(acc[mt][nt], afr[mt], bfr[nt]);

            // producer interleave: one 16B tanh store per ks
            if (more) {
                if (ks == 0) tanh_store(a00, t00, aoff0, 0, s ^ 1);
                if (ks == 1) tanh_store(a01, t01, aoff0, 1, s ^ 1);
                if (ks == 2) tanh_store(a10, t10, aoff1, 0, s ^ 1);
                if (ks == 3) tanh_store(a11, t11, aoff1, 1, s ^ 1);
            }
        }
    }

    // ---- epilogue: + bias, fp32 stores ----
#pragma unroll
    for (int nt = 0; nt < 8; nt++) {
        int col = n0 + warp_n * 64 + nt * 8 + (lane & 3) * 2;
        float bj0 = b_j[col], bj1 = b_j[col + 1];
#pragma unroll
        for (int mt = 0; mt < 4; mt++) {
            int r0 = m0 + warp_m * 64 + mt * 16 + (lane >> 2);
            float* p = out + (size_t)r0 * NCLS + col;
            *(float2*)p              = make_float2(acc[mt][nt][0] + bj0, acc[mt][nt][1] + bj1);
            *(float2*)(p + 8 * NCLS) = make_float2(acc[mt][nt][2] + bj0, acc[mt][nt][3] + bj1);
        }
    }
}

// ---------------------------------------------------------------------------
extern "C" void kernel_launch(void* const* d_in, const int* in_sizes, int n_in,
                              void* d_out, int out_size) {
    const float* audio = (const float*)d_in[0];
    const float* text  = (const float*)d_in[1];
    const float* W_a   = (const float*)d_in[2];
    const float* b_a   = (const float*)d_in[3];
    const float* W_t   = (const float*)d_in[4];
    const float* b_t   = (const float*)d_in[5];
    const float* W_j   = (const float*)d_in[6];
    const float* b_j   = (const float*)d_in[7];
    float* out = (float*)d_out;

    prep_kernel<<<1670, 256>>>(audio, text, W_a, b_a, W_t, b_t, W_j);

    cudaFuncSetAttribute(joint_main_kernel, cudaFuncAttributeMaxDynamicSharedMemorySize,
                         SMEM_BYTES);
    joint_main_kernel<<<dim3(1600, 2), THREADS, SMEM_BYTES>>>(b_j, out);
}

// round 12
// speedup vs baseline: 1.2376x; 1.2376x over previous
#include <cuda_runtime.h>
#include <cuda_fp16.h>
#include <cstdint>

// ---------------------------------------------------------------------------
// JointNetwork: out[b,t,u,:] = tanh(a[bt,:] + t[bu,:]) @ W_j + b_j
//   big GEMM: M=204800, K=640, N=512, fp32 out
// R11: fix R10 swizzle-offset bug: swz(off+ks*32) = swz(off) ^ (ks*32)
//      (XOR, not ADD — the add carries across the swizzled bit 7).
//      CTA tile M64xN512 (512 thr, 16 warps 2x8), warp tile M32xN64.
// ---------------------------------------------------------------------------
#define HID   640
#define NCLS  512

__device__ __half g_a[2048 * HID];   // audio projection, fp16
__device__ __half g_t[400 * HID];    // text projection, fp16
__device__ __half g_wj[NCLS * HID];  // W_j^T as [v][h] (K-major B rows), fp16

// SMEM: A stages 8KB @ {0,8K}; B stages 64KB @ {16K,80K}; total 144KB
#define SA_STAGE(s) ((uint32_t)(s) * 8192u)
#define SB_STAGE(s) (16384u + (uint32_t)(s) * 65536u)
#define SMEM_BYTES  147456u

// ---------------------------------------------------------------------------
__device__ __forceinline__ uint32_t smem_u32(const void* p) {
    uint32_t a;
    asm("{ .reg .u64 t; cvta.to.shared.u64 t, %1; cvt.u32.u64 %0, t; }" : "=r"(a) : "l"(p));
    return a;
}
__device__ __forceinline__ uint32_t swz128(uint32_t off) { return off ^ ((off >> 3) & 0x70); }

__device__ __forceinline__ float tanh_fast(float x) {
    float e;
    asm("ex2.approx.f32 %0, %1;" : "=f"(e) : "f"(x * 2.8853900817779268f)); // e^{2x}
    float r;
    asm("rcp.approx.f32 %0, %1;" : "=f"(r) : "f"(e + 1.0f));
    return fmaf(-2.0f, r, 1.0f);
}

#define CP_ASYNC16(dst_u32, src_ptr) \
    asm volatile("cp.async.cg.shared.global [%0], [%1], 16;" \
        :: "r"(dst_u32), "l"(src_ptr) : "memory")
#define CP_ASYNC_COMMIT() asm volatile("cp.async.commit_group;" ::: "memory")
#define CP_ASYNC_WAIT0()  asm volatile("cp.async.wait_group 0;" ::: "memory")

#define LDSM_X4(r0, r1, r2, r3, addr) \
    asm volatile("ldmatrix.sync.aligned.m8n8.x4.shared.b16 {%0,%1,%2,%3}, [%4];" \
        : "=r"(r0), "=r"(r1), "=r"(r2), "=r"(r3) : "r"(addr))

#define MMA16816(d, a, b) \
    asm volatile("mma.sync.aligned.m16n8k16.row.col.f32.f16.f16.f32 " \
        "{%0,%1,%2,%3}, {%4,%5,%6,%7}, {%8,%9}, {%0,%1,%2,%3};" \
        : "+f"((d)[0]), "+f"((d)[1]), "+f"((d)[2]), "+f"((d)[3]) \
        : "r"((a)[0]), "r"((a)[1]), "r"((a)[2]), "r"((a)[3]), "r"((b)[0]), "r"((b)[1]))

// ---------------------------------------------------------------------------
// Fused prep: blocks [0,320) audio proj, [320,390) text proj, [390,1670) Wj cvt
// ---------------------------------------------------------------------------
__device__ void sgemm_body(const float* __restrict__ A, const float* __restrict__ W,
                           const float* __restrict__ bias, __half* __restrict__ C,
                           int M, int K, int bx, int by)
{
    __shared__ float As[16][68];
    __shared__ float Bs[16][64];
    const int N = HID;
    int tid = threadIdx.x;
    int bm = by * 64, bn = bx * 64;
    int tx = tid & 15, ty = tid >> 4;
    int ar = tid >> 2, ak = (tid & 3) * 4;
    int bk = tid >> 4, bn4 = (tid & 15) * 4;
    float acc[4][4] = {};

    for (int k0 = 0; k0 < K; k0 += 16) {
        float4 av = make_float4(0.f, 0.f, 0.f, 0.f);
        if (bm + ar < M) av = *(const float4*)(A + (size_t)(bm + ar) * K + k0 + ak);
        As[ak + 0][ar] = av.x; As[ak + 1][ar] = av.y;
        As[ak + 2][ar] = av.z; As[ak + 3][ar] = av.w;
        *(float4*)&Bs[bk][bn4] = *(const float4*)(W + (size_t)(k0 + bk) * N + bn + bn4);
        __syncthreads();
#pragma unroll
        for (int k = 0; k < 16; k++) {
            float4 a4 = *(const float4*)&As[k][ty * 4];
            float4 b4 = *(const float4*)&Bs[k][tx * 4];
            float aa[4] = {a4.x, a4.y, a4.z, a4.w};
            float bb[4] = {b4.x, b4.y, b4.z, b4.w};
#pragma unroll
            for (int i = 0; i < 4; i++)
#pragma unroll
                for (int j = 0; j < 4; j++) acc[i][j] += aa[i] * bb[j];
        }
        __syncthreads();
    }
#pragma unroll
    for (int i = 0; i < 4; i++) {
        int m = bm + ty * 4 + i;
        if (m < M) {
#pragma unroll
            for (int j = 0; j < 4; j++) {
                int n = bn + tx * 4 + j;
                C[(size_t)m * N + n] = __float2half_rn(acc[i][j] + bias[n]);
            }
        }
    }
}

__global__ __launch_bounds__(256) void prep_kernel(
    const float* __restrict__ audio, const float* __restrict__ text,
    const float* __restrict__ W_a, const float* __restrict__ b_a,
    const float* __restrict__ W_t, const float* __restrict__ b_t,
    const float* __restrict__ W_j)
{
    int blk = blockIdx.x;
    if (blk < 320) {
        sgemm_body(audio, W_a, b_a, g_a, 2048, 512, blk % 10, blk / 10);
    } else if (blk < 390) {
        int b = blk - 320;
        sgemm_body(text, W_t, b_t, g_t, 400, 320, b % 10, b / 10);
    } else {
        int idx = (blk - 390) * 256 + threadIdx.x;   // [0, 327680)
        int v = idx / HID;
        int h = idx - v * HID;
        g_wj[idx] = __float2half_rn(W_j[h * NCLS + v]);
    }
}

// ---------------------------------------------------------------------------
// Main HMMA kernel: 512 thr (16 warps, 2x8), CTA tile M64 x N512,
// warp tile M32 x N64, K in 10 chunks of 64, double-buffered.
// ---------------------------------------------------------------------------
static constexpr int THREADS = 512;
static constexpr int KCHUNKS = 10;

__global__ __launch_bounds__(THREADS, 1) void joint_main_kernel(
    const float* __restrict__ b_j, float* __restrict__ out)
{
    extern __shared__ __align__(1024) char smem[];
    const uint32_t sb = smem_u32(smem);
    const int tid  = threadIdx.x;
    const int lane = tid & 31;
    const int wid  = tid >> 5;
    const int warp_m = wid & 1;    // 0..1 (32-row slab)
    const int warp_n = wid >> 1;   // 0..7 (64-col slab)
    const int m0 = blockIdx.x * 64;

    // producer: 512 tasks of 16B (64 rows x 8 units); exactly one per thread
    const int pr = tid >> 3;          // row 0..63
    const int pj = tid & 7;           // 16B unit (8 halves) in 128B row
    const int m   = m0 + pr;
    const int bt  = m / 100;
    const int u   = m - bt * 100;
    const __half* rowa = g_a + bt * HID + pj * 8;
    const __half* rowt = g_t + (((bt >> 9) * 100) + u) * HID + pj * 8;
    const uint32_t a_soff = swz128((uint32_t)(pr * 128 + pj * 16));  // fixed per thread

    // B cp.async mapping: 8 x 16B per thread per chunk (512 rows x 8 units)
    const int b_row0  = tid >> 3;     // 0..63, +64 per i
    const int b_chunk = tid & 7;
    const __half* wj_base = g_wj + (size_t)b_row0 * HID + b_chunk * 8;

    // precomputed swizzled LDSM offsets (ks=0); swz(off + ks*32) = swz(off) ^ (ks*32)
    // (un-swizzled column bits [5:6] are zero, so the add is a disjoint OR and
    //  commutes with the XOR swizzle as an XOR)
    uint32_t offA[2], offB[4];
    {
        const int tl = lane >> 3, rr = lane & 7;
#pragma unroll
        for (int mt = 0; mt < 2; mt++) {
            int row = warp_m * 32 + mt * 16 + (lane & 15);
            offA[mt] = swz128((uint32_t)(row * 128 + (lane >> 4) * 16));
        }
#pragma unroll
        for (int p = 0; p < 4; p++) {
            int row = warp_n * 64 + p * 16 + (tl >> 1) * 8 + rr;
            offB[p] = swz128((uint32_t)(row * 128 + (tl & 1) * 16));
        }
    }

    float acc[2][8][4];
#pragma unroll
    for (int mt = 0; mt < 2; mt++)
#pragma unroll
        for (int nt = 0; nt < 8; nt++)
#pragma unroll
            for (int q = 0; q < 4; q++) acc[mt][nt][q] = 0.f;

    auto loadB = [&](int c, int s) {
        const __half* src = wj_base + c * 64;
#pragma unroll
        for (int i = 0; i < 8; i++) {
            uint32_t off = (uint32_t)((b_row0 + i * 64) * 128 + b_chunk * 16);
            CP_ASYNC16(sb + SB_STAGE(s) + swz128(off), src + (size_t)i * 64 * HID);
        }
        CP_ASYNC_COMMIT();
    };

    // tanh 8 halves (one 16B unit) into stage s
    auto tanh_store = [&](uint4 av, uint4 tv, int s) {
        const __half2* ah = (const __half2*)&av;
        const __half2* th = (const __half2*)&tv;
        uint32_t rs[4];
#pragma unroll
        for (int q = 0; q < 4; q++) {
            float2 af = __half22float2(ah[q]);
            float2 tf = __half22float2(th[q]);
            __half2 h = __floats2half2_rn(tanh_fast(af.x + tf.x), tanh_fast(af.y + tf.y));
            rs[q] = *(uint32_t*)&h;
        }
        *(uint4*)(smem + SA_STAGE(s) + a_soff) = make_uint4(rs[0], rs[1], rs[2], rs[3]);
    };

    // ---- prologue: produce chunk 0, start B chunk 0 ----
    {
        uint4 av = *(const uint4*)rowa;
        uint4 tv = *(const uint4*)rowt;
        tanh_store(av, tv, 0);
    }
    loadB(0, 0);

    // ---- main loop ----
    for (int c = 0; c < KCHUNKS; c++) {
        const int s = c & 1;
        CP_ASYNC_WAIT0();
        __syncthreads();                 // stage s ready; stage s^1 free

        const bool more = (c + 1 < KCHUNKS);
        if (more) loadB(c + 1, s ^ 1);

        uint4 av, tv;
        if (more) {
            av = *(const uint4*)(rowa + (c + 1) * 64);
            tv = *(const uint4*)(rowt + (c + 1) * 64);
        }

        const uint32_t aBase = sb + SA_STAGE(s);
        const uint32_t bBase = sb + SB_STAGE(s);

#pragma unroll
        for (int ks = 0; ks < 4; ks++) {
            const uint32_t kso = (uint32_t)ks * 32u;
            uint32_t afr[2][4];
#pragma unroll
            for (int mt = 0; mt < 2; mt++)
                LDSM_X4(afr[mt][0], afr[mt][1], afr[mt][2], afr[mt][3],
                        aBase + (offA[mt] ^ kso));
            uint32_t bfr[8][2];
#pragma unroll
            for (int p = 0; p < 4; p++) {
                uint32_t r0, r1, r2, r3;
                LDSM_X4(r0, r1, r2, r3, bBase + (offB[p] ^ kso));
                bfr[p * 2 + 0][0] = r0; bfr[p * 2 + 0][1] = r1;
                bfr[p * 2 + 1][0] = r2; bfr[p * 2 + 1][1] = r3;
            }

#pragma unroll
            for (int mt = 0; mt < 2; mt++)
#pragma unroll
                for (int nt = 0; nt < 8; nt++)
                    MMA16816(acc[mt][nt], afr[mt], bfr[nt]);

            if (ks == 1 && more) tanh_store(av, tv, s ^ 1);
        }
    }

    // ---- epilogue: + bias, fp32 stores ----
#pragma unroll
    for (int nt = 0; nt < 8; nt++) {
        int col = warp_n * 64 + nt * 8 + (lane & 3) * 2;
        float bj0 = b_j[col], bj1 = b_j[col + 1];
#pragma unroll
        for (int mt = 0; mt < 2; mt++) {
            int r0 = m0 + warp_m * 32 + mt * 16 + (lane >> 2);
            float* p = out + (size_t)r0 * NCLS + col;
            *(float2*)p              = make_float2(acc[mt][nt][0] + bj0, acc[mt][nt][1] + bj1);
            *(float2*)(p + 8 * NCLS) = make_float2(acc[mt][nt][2] + bj0, acc[mt][nt][3] + bj1);
        }
    }
}

// ---------------------------------------------------------------------------
extern "C" void kernel_launch(void* const* d_in, const int* in_sizes, int n_in,
                              void* d_out, int out_size) {
    const float* audio = (const float*)d_in[0];
    const float* text  = (const float*)d_in[1];
    const float* W_a   = (const float*)d_in[2];
    const float* b_a   = (const float*)d_in[3];
    const float* W_t   = (const float*)d_in[4];
    const float* b_t   = (const float*)d_in[5];
    const float* W_j   = (const float*)d_in[6];
    const float* b_j   = (const float*)d_in[7];
    float* out = (float*)d_out;

    prep_kernel<<<1670, 256>>>(audio, text, W_a, b_a, W_t, b_t, W_j);

    cudaFuncSetAttribute(joint_main_kernel, cudaFuncAttributeMaxDynamicSharedMemorySize,
                         SMEM_BYTES);
    joint_main_kernel<<<3200, THREADS, SMEM_BYTES>>>(b_j, out);
}

// round 13
// speedup vs baseline: 1.3545x; 1.0944x over previous
#include <cuda_runtime.h>
#include <cuda_fp16.h>
#include <cstdint>

// ---------------------------------------------------------------------------
// JointNetwork: out[b,t,u,:] = tanh(a[bt,:] + t[bu,:]) @ W_j + b_j
//   big GEMM: M=204800, K=640, N=512, fp32 out
// R12: prep pipeline HMMA-ized (was 61us SIMT fp32):
//   convert_kernel: fp16 copies of audio/text + transposed fp16 W_a/W_t/W_j
//   proj_kernel:    HMMA GEMM (M64xN128 CTA) for both projections
// Main kernel unchanged from R11 (455us, tensor 48.6%).
// ---------------------------------------------------------------------------
#define HID   640
#define NCLS  512

// fp16 scratch (device globals; zero-initialized at load)
__device__ __half g_a[2048 * HID];    // audio projection out, fp16
__device__ __half g_t[448 * HID];     // text projection out, fp16 (padded rows)
__device__ __half g_wj[NCLS * HID];   // W_j^T [v][h], K-major rows
__device__ __half g_ah[2048 * 512];   // audio input, fp16
__device__ __half g_th[448 * 320];    // text input, fp16 (rows 400+ stay zero)
__device__ __half g_waT[HID * 512];   // W_a^T [n][k]
__device__ __half g_wtT[HID * 320];   // W_t^T [n][k]

// Main kernel SMEM: A stages 8KB @ {0,8K}; B stages 64KB @ {16K,80K}; 144KB
#define SA_STAGE(s) ((uint32_t)(s) * 8192u)
#define SB_STAGE(s) (16384u + (uint32_t)(s) * 65536u)
#define SMEM_BYTES  147456u

// ---------------------------------------------------------------------------
__device__ __forceinline__ uint32_t smem_u32(const void* p) {
    uint32_t a;
    asm("{ .reg .u64 t; cvta.to.shared.u64 t, %1; cvt.u32.u64 %0, t; }" : "=r"(a) : "l"(p));
    return a;
}
__device__ __forceinline__ uint32_t swz128(uint32_t off) { return off ^ ((off >> 3) & 0x70); }

__device__ __forceinline__ float tanh_fast(float x) {
    float e;
    asm("ex2.approx.f32 %0, %1;" : "=f"(e) : "f"(x * 2.8853900817779268f)); // e^{2x}
    float r;
    asm("rcp.approx.f32 %0, %1;" : "=f"(r) : "f"(e + 1.0f));
    return fmaf(-2.0f, r, 1.0f);
}

#define CP_ASYNC16(dst_u32, src_ptr) \
    asm volatile("cp.async.cg.shared.global [%0], [%1], 16;" \
        :: "r"(dst_u32), "l"(src_ptr) : "memory")
#define CP_ASYNC_COMMIT() asm volatile("cp.async.commit_group;" ::: "memory")
#define CP_ASYNC_WAIT0()  asm volatile("cp.async.wait_group 0;" ::: "memory")

#define LDSM_X4(r0, r1, r2, r3, addr) \
    asm volatile("ldmatrix.sync.aligned.m8n8.x4.shared.b16 {%0,%1,%2,%3}, [%4];" \
        : "=r"(r0), "=r"(r1), "=r"(r2), "=r"(r3) : "r"(addr))

#define MMA16816(d, a, b) \
    asm volatile("mma.sync.aligned.m16n8k16.row.col.f32.f16.f16.f32 " \
        "{%0,%1,%2,%3}, {%4,%5,%6,%7}, {%8,%9}, {%0,%1,%2,%3};" \
        : "+f"((d)[0]), "+f"((d)[1]), "+f"((d)[2]), "+f"((d)[3]) \
        : "r"((a)[0]), "r"((a)[1]), "r"((a)[2]), "r"((a)[3]), "r"((b)[0]), "r"((b)[1]))

// ---------------------------------------------------------------------------
// convert_kernel: fp32 -> fp16 copies / transposes (dest-linear indexing)
//   [0,O1): audio flat; [O1,O2): text flat; [O2,O3): W_a^T; [O3,O4): W_t^T;
//   [O4,END): W_j^T
// ---------------------------------------------------------------------------
static constexpr int O1 = 1048576;            // 2048*512
static constexpr int O2 = O1 + 128000;        // + 400*320
static constexpr int O3 = O2 + 327680;        // + 640*512
static constexpr int O4 = O3 + 204800;        // + 640*320
static constexpr int CEND = O4 + 327680;      // + 512*640
static constexpr int CONV_BLOCKS = (CEND + 255) / 256;

__global__ __launch_bounds__(256) void convert_kernel(
    const float* __restrict__ audio, const float* __restrict__ text,
    const float* __restrict__ W_a, const float* __restrict__ W_t,
    const float* __restrict__ W_j)
{
    int idx = blockIdx.x * 256 + threadIdx.x;
    if (idx >= CEND) return;
    if (idx < O1) {
        g_ah[idx] = __float2half_rn(audio[idx]);
    } else if (idx < O2) {
        int d = idx - O1;
        g_th[d] = __float2half_rn(text[d]);          // rows 400..447 never touched
    } else if (idx < O3) {
        int d = idx - O2;
        int n = d / 512, k = d - n * 512;
        g_waT[d] = __float2half_rn(W_a[k * HID + n]);
    } else if (idx < O4) {
        int d = idx - O3;
        int n = d / 320, k = d - n * 320;
        g_wtT[d] = __float2half_rn(W_t[k * HID + n]);
    } else {
        int d = idx - O4;
        int v = d / HID, h = d - v * HID;
        g_wj[d] = __float2half_rn(W_j[h * NCLS + v]);
    }
}

// ---------------------------------------------------------------------------
// proj_kernel: C[M,HID] = A[M,K] @ W + bias (fp16 in/out, fp32 accum, HMMA)
//   CTA tile M64 x N128, 256 thr (8 warps, 2x4), warp tile M32 x N32.
//   blocks [0,160): audio (2048/64 x 640/128); [160,195): text (448/64 x 5)
//   SMEM: A 8KB x2 @ {0,8K}; B 16KB x2 @ {16K,32K}; 48KB static.
// ---------------------------------------------------------------------------
__global__ __launch_bounds__(256) void proj_kernel(
    const float* __restrict__ b_a, const float* __restrict__ b_t)
{
    __shared__ __align__(1024) char psm[49152];
    const uint32_t sb = smem_u32(psm);
    const int tid  = threadIdx.x;
    const int lane = tid & 31;
    const int wid  = tid >> 5;
    const int warp_m = wid & 1;   // 0..1 (32-row slab)
    const int warp_n = wid >> 1;  // 0..3 (32-col slab)

    const __half* Ap; const __half* Wp; const float* bias; __half* Cp;
    int lda, Kd, kch, m0, n0;
    {
        int blk = blockIdx.x;
        if (blk < 160) {
            int my = blk / 5, nx = blk - my * 5;
            Ap = g_ah; lda = 512; Wp = g_waT; Kd = 512; kch = 8;
            bias = b_a; Cp = g_a; m0 = my * 64; n0 = nx * 128;
        } else {
            int b = blk - 160;
            int my = b / 5, nx = b - my * 5;
            Ap = g_th; lda = 320; Wp = g_wtT; Kd = 320; kch = 5;
            bias = b_t; Cp = g_t; m0 = my * 64; n0 = nx * 128;
        }
    }

    const int lr = tid >> 3;         // 0..31
    const int lj = tid & 7;          // 16B unit
    const __half* a_src = Ap + (size_t)(m0 + lr) * lda + lj * 8;
    const __half* b_src = Wp + (size_t)(n0 + lr) * Kd + lj * 8;

    auto loadAB = [&](int kc, int s) {
        const int ko = kc * 64;
#pragma unroll
        for (int i = 0; i < 2; i++) {   // A: 64 rows
            uint32_t off = (uint32_t)((lr + i * 32) * 128 + lj * 16);
            CP_ASYNC16(sb + (uint32_t)(s * 8192) + swz128(off),
                       a_src + (size_t)i * 32 * lda + ko);
        }
#pragma unroll
        for (int i = 0; i < 4; i++) {   // B: 128 rows
            uint32_t off = (uint32_t)((lr + i * 32) * 128 + lj * 16);
            CP_ASYNC16(sb + 16384u + (uint32_t)(s * 16384) + swz128(off),
                       b_src + (size_t)i * 32 * Kd + ko);
        }
        CP_ASYNC_COMMIT();
    };

    uint32_t offA[2], offB[2];
    {
        const int tl = lane >> 3, rr = lane & 7;
#pragma unroll
        for (int mt = 0; mt < 2; mt++) {
            int row = warp_m * 32 + mt * 16 + (lane & 15);
            offA[mt] = swz128((uint32_t)(row * 128 + (lane >> 4) * 16));
        }
#pragma unroll
        for (int p = 0; p < 2; p++) {
            int row = warp_n * 32 + p * 16 + (tl >> 1) * 8 + rr;
            offB[p] = swz128((uint32_t)(row * 128 + (tl & 1) * 16));
        }
    }

    float acc[2][4][4];
#pragma unroll
    for (int mt = 0; mt < 2; mt++)
#pragma unroll
        for (int nt = 0; nt < 4; nt++)
#pragma unroll
            for (int q = 0; q < 4; q++) acc[mt][nt][q] = 0.f;

    loadAB(0, 0);
    for (int c = 0; c < kch; c++) {
        const int s = c & 1;
        CP_ASYNC_WAIT0();
        __syncthreads();
        if (c + 1 < kch) loadAB(c + 1, s ^ 1);

        const uint32_t aBase = sb + (uint32_t)(s * 8192);
        const uint32_t bBase = sb + 16384u + (uint32_t)(s * 16384);
#pragma unroll
        for (int ks = 0; ks < 4; ks++) {
            const uint32_t kso = (uint32_t)ks * 32u;
            uint32_t afr[2][4];
#pragma unroll
            for (int mt = 0; mt < 2; mt++)
                LDSM_X4(afr[mt][0], afr[mt][1], afr[mt][2], afr[mt][3],
                        aBase + (offA[mt] ^ kso));
            uint32_t bfr[4][2];
#pragma unroll
            for (int p = 0; p < 2; p++) {
                uint32_t r0, r1, r2, r3;
                LDSM_X4(r0, r1, r2, r3, bBase + (offB[p] ^ kso));
                bfr[p * 2 + 0][0] = r0; bfr[p * 2 + 0][1] = r1;
                bfr[p * 2 + 1][0] = r2; bfr[p * 2 + 1][1] = r3;
            }
#pragma unroll
            for (int mt = 0; mt < 2; mt++)
#pragma unroll
                for (int nt = 0; nt < 4; nt++)
                    MMA16816(acc[mt][nt], afr[mt], bfr[nt]);
        }
    }

    // epilogue: + bias, fp16 stores (half2)
#pragma unroll
    for (int nt = 0; nt < 4; nt++) {
        int col = n0 + warp_n * 32 + nt * 8 + (lane & 3) * 2;
        float bj0 = bias[col], bj1 = bias[col + 1];
#pragma unroll
        for (int mt = 0; mt < 2; mt++) {
            int r0 = m0 + warp_m * 32 + mt * 16 + (lane >> 2);
            __half2* p0 = (__half2*)(Cp + (size_t)r0 * HID + col);
            __half2* p1 = (__half2*)(Cp + (size_t)(r0 + 8) * HID + col);
            *p0 = __floats2half2_rn(acc[mt][nt][0] + bj0, acc[mt][nt][1] + bj1);
            *p1 = __floats2half2_rn(acc[mt][nt][2] + bj0, acc[mt][nt][3] + bj1);
        }
    }
}

// ---------------------------------------------------------------------------
// Main HMMA kernel (unchanged from R11): 512 thr (16 warps, 2x8),
// CTA tile M64 x N512, warp tile M32 x N64, K in 10 chunks of 64.
// ---------------------------------------------------------------------------
static constexpr int THREADS = 512;
static constexpr int KCHUNKS = 10;

__global__ __launch_bounds__(THREADS, 1) void joint_main_kernel(
    const float* __restrict__ b_j, float* __restrict__ out)
{
    extern __shared__ __align__(1024) char smem[];
    const uint32_t sb = smem_u32(smem);
    const int tid  = threadIdx.x;
    const int lane = tid & 31;
    const int wid  = tid >> 5;
    const int warp_m = wid & 1;    // 0..1 (32-row slab)
    const int warp_n = wid >> 1;   // 0..7 (64-col slab)
    const int m0 = blockIdx.x * 64;

    // producer: 512 tasks of 16B (64 rows x 8 units); one per thread
    const int pr = tid >> 3;
    const int pj = tid & 7;
    const int m   = m0 + pr;
    const int bt  = m / 100;
    const int u   = m - bt * 100;
    const __half* rowa = g_a + bt * HID + pj * 8;
    const __half* rowt = g_t + (((bt >> 9) * 100) + u) * HID + pj * 8;
    const uint32_t a_soff = swz128((uint32_t)(pr * 128 + pj * 16));

    // B cp.async mapping: 8 x 16B per thread per chunk
    const int b_row0  = tid >> 3;
    const int b_chunk = tid & 7;
    const __half* wj_base = g_wj + (size_t)b_row0 * HID + b_chunk * 8;

    // precomputed swizzled LDSM offsets; swz(off + ks*32) = swz(off) ^ (ks*32)
    uint32_t offA[2], offB[4];
    {
        const int tl = lane >> 3, rr = lane & 7;
#pragma unroll
        for (int mt = 0; mt < 2; mt++) {
            int row = warp_m * 32 + mt * 16 + (lane & 15);
            offA[mt] = swz128((uint32_t)(row * 128 + (lane >> 4) * 16));
        }
#pragma unroll
        for (int p = 0; p < 4; p++) {
            int row = warp_n * 64 + p * 16 + (tl >> 1) * 8 + rr;
            offB[p] = swz128((uint32_t)(row * 128 + (tl & 1) * 16));
        }
    }

    float acc[2][8][4];
#pragma unroll
    for (int mt = 0; mt < 2; mt++)
#pragma unroll
        for (int nt = 0; nt < 8; nt++)
#pragma unroll
            for (int q = 0; q < 4; q++) acc[mt][nt][q] = 0.f;

    auto loadB = [&](int c, int s) {
        const __half* src = wj_base + c * 64;
#pragma unroll
        for (int i = 0; i < 8; i++) {
            uint32_t off = (uint32_t)((b_row0 + i * 64) * 128 + b_chunk * 16);
            CP_ASYNC16(sb + SB_STAGE(s) + swz128(off), src + (size_t)i * 64 * HID);
        }
        CP_ASYNC_COMMIT();
    };

    auto tanh_store = [&](uint4 av, uint4 tv, int s) {
        const __half2* ah = (const __half2*)&av;
        const __half2* th = (const __half2*)&tv;
        uint32_t rs[4];
#pragma unroll
        for (int q = 0; q < 4; q++) {
            float2 af = __half22float2(ah[q]);
            float2 tf = __half22float2(th[q]);
            __half2 h = __floats2half2_rn(tanh_fast(af.x + tf.x), tanh_fast(af.y + tf.y));
            rs[q] = *(uint32_t*)&h;
        }
        *(uint4*)(smem + SA_STAGE(s) + a_soff) = make_uint4(rs[0], rs[1], rs[2], rs[3]);
    };

    {
        uint4 av = *(const uint4*)rowa;
        uint4 tv = *(const uint4*)rowt;
        tanh_store(av, tv, 0);
    }
    loadB(0, 0);

    for (int c = 0; c < KCHUNKS; c++) {
        const int s = c & 1;
        CP_ASYNC_WAIT0();
        __syncthreads();

        const bool more = (c + 1 < KCHUNKS);
        if (more) loadB(c + 1, s ^ 1);

        uint4 av, tv;
        if (more) {
            av = *(const uint4*)(rowa + (c + 1) * 64);
            tv = *(const uint4*)(rowt + (c + 1) * 64);
        }

        const uint32_t aBase = sb + SA_STAGE(s);
        const uint32_t bBase = sb + SB_STAGE(s);

#pragma unroll
        for (int ks = 0; ks < 4; ks++) {
            const uint32_t kso = (uint32_t)ks * 32u;
            uint32_t afr[2][4];
#pragma unroll
            for (int mt = 0; mt < 2; mt++)
                LDSM_X4(afr[mt][0], afr[mt][1], afr[mt][2], afr[mt][3],
                        aBase + (offA[mt] ^ kso));
            uint32_t bfr[8][2];
#pragma unroll
            for (int p = 0; p < 4; p++) {
                uint32_t r0, r1, r2, r3;
                LDSM_X4(r0, r1, r2, r3, bBase + (offB[p] ^ kso));
                bfr[p * 2 + 0][0] = r0; bfr[p * 2 + 0][1] = r1;
                bfr[p * 2 + 1][0] = r2; bfr[p * 2 + 1][1] = r3;
            }

#pragma unroll
            for (int mt = 0; mt < 2; mt++)
#pragma unroll
                for (int nt = 0; nt < 8; nt++)
                    MMA16816(acc[mt][nt], afr[mt], bfr[nt]);

            if (ks == 1 && more) tanh_store(av, tv, s ^ 1);
        }
    }

    // epilogue: + bias, fp32 stores
#pragma unroll
    for (int nt = 0; nt < 8; nt++) {
        int col = warp_n * 64 + nt * 8 + (lane & 3) * 2;
        float bj0 = b_j[col], bj1 = b_j[col + 1];
#pragma unroll
        for (int mt = 0; mt < 2; mt++) {
            int r0 = m0 + warp_m * 32 + mt * 16 + (lane >> 2);
            float* p = out + (size_t)r0 * NCLS + col;
            *(float2*)p              = make_float2(acc[mt][nt][0] + bj0, acc[mt][nt][1] + bj1);
            *(float2*)(p + 8 * NCLS) = make_float2(acc[mt][nt][2] + bj0, acc[mt][nt][3] + bj1);
        }
    }
}

// ---------------------------------------------------------------------------
extern "C" void kernel_launch(void* const* d_in, const int* in_sizes, int n_in,
                              void* d_out, int out_size) {
    const float* audio = (const float*)d_in[0];
    const float* text  = (const float*)d_in[1];
    const float* W_a   = (const float*)d_in[2];
    const float* b_a   = (const float*)d_in[3];
    const float* W_t   = (const float*)d_in[4];
    const float* b_t   = (const float*)d_in[5];
    const float* W_j   = (const float*)d_in[6];
    const float* b_j   = (const float*)d_in[7];
    float* out = (float*)d_out;

    convert_kernel<<<CONV_BLOCKS, 256>>>(audio, text, W_a, W_t, W_j);
    proj_kernel<<<195, 256>>>(b_a, b_t);

    cudaFuncSetAttribute(joint_main_kernel, cudaFuncAttributeMaxDynamicSharedMemorySize,
                         SMEM_BYTES);
    joint_main_kernel<<<3200, THREADS, SMEM_BYTES>>>(b_j, out);
}